// round 1
// baseline (speedup 1.0000x reference)
#include <cuda_runtime.h>
#include <cuda_bf16.h>
#include <math.h>

// ---------------- problem constants ----------------
#define B_    2
#define NQ_   5376
#define NV_   5376
#define C_    256
#define HEADS_ 8
#define HD_   32
#define LEVELS_ 3
#define POINTS_ 4
#define K_DIM 256
#define M_ROWS (B_ * NQ_)   // 10752

// level shapes
// lvl0: 64x64 start 0, lvl1: 32x32 start 4096, lvl2: 16x16 start 5120

// ---------------- scratch (no allocations allowed) ----------------
__device__ float g_v[(size_t)B_ * NV_ * C_];          // value @ Wv^T + bv
__device__ float g_off[(size_t)B_ * NQ_ * 192];       // query @ Woff^T + boff
__device__ float g_attn[(size_t)B_ * NQ_ * 96];       // query @ Wa^T + ba (pre-softmax)
__device__ float g_tmp[(size_t)B_ * NQ_ * C_];        // sampled output (b,q,h,d)

// ---------------- tiled fp32 GEMM: C = A(MxK) * W(NxK)^T + bias ----------------
// BM=64, BN=64, BK=16, 256 threads, 4x4 per-thread tile
template<int BM, int BN, int BK, int TM, int TN>
__global__ void gemm_bias_tn(const float* __restrict__ A,
                             const float* __restrict__ W,
                             const float* __restrict__ bias,
                             float* __restrict__ C,
                             int M, int N, int K)
{
    __shared__ float As[BK][BM];
    __shared__ float Ws[BK][BN + 1];

    const int tid = threadIdx.x;
    const int tx = tid % (BN / TN);     // 0..15
    const int ty = tid / (BN / TN);     // 0..15
    const int block_m = blockIdx.y * BM;
    const int block_n = blockIdx.x * BN;

    float acc[TM][TN];
    #pragma unroll
    for (int i = 0; i < TM; i++)
        #pragma unroll
        for (int j = 0; j < TN; j++) acc[i][j] = 0.f;

    for (int k0 = 0; k0 < K; k0 += BK) {
        // A tile: BM x BK
        #pragma unroll
        for (int i = tid; i < BM * BK; i += 256) {
            int m = i / BK, kk = i % BK;
            int gm = block_m + m;
            As[kk][m] = (gm < M) ? A[(size_t)gm * K + k0 + kk] : 0.f;
        }
        // W tile: BN x BK
        #pragma unroll
        for (int i = tid; i < BN * BK; i += 256) {
            int n = i / BK, kk = i % BK;
            int gn = block_n + n;
            Ws[kk][n] = (gn < N) ? W[(size_t)gn * K + k0 + kk] : 0.f;
        }
        __syncthreads();

        #pragma unroll
        for (int kk = 0; kk < BK; kk++) {
            float a_frag[TM], w_frag[TN];
            #pragma unroll
            for (int i = 0; i < TM; i++) a_frag[i] = As[kk][ty * TM + i];
            #pragma unroll
            for (int j = 0; j < TN; j++) w_frag[j] = Ws[kk][tx * TN + j];
            #pragma unroll
            for (int i = 0; i < TM; i++)
                #pragma unroll
                for (int j = 0; j < TN; j++)
                    acc[i][j] = fmaf(a_frag[i], w_frag[j], acc[i][j]);
        }
        __syncthreads();
    }

    #pragma unroll
    for (int i = 0; i < TM; i++) {
        int gm = block_m + ty * TM + i;
        if (gm >= M) continue;
        #pragma unroll
        for (int j = 0; j < TN; j++) {
            int gn = block_n + tx * TN + j;
            if (gn < N)
                C[(size_t)gm * N + gn] = acc[i][j] + bias[gn];
        }
    }
}

// ---------------- sampling kernel: one warp per (b*NQ, head) ----------------
__global__ void msda_sample_kernel(const float* __restrict__ v,
                                   const float* __restrict__ ref,
                                   const float* __restrict__ off,
                                   const float* __restrict__ attn,
                                   float* __restrict__ out)
{
    const int warp = (blockIdx.x * blockDim.x + threadIdx.x) >> 5;
    const int lane = threadIdx.x & 31;
    const int total = B_ * NQ_ * HEADS_;
    if (warp >= total) return;

    const int head = warp % HEADS_;
    const int bq   = warp / HEADS_;
    const int b    = bq / NQ_;

    // ---- softmax over 12 logits (head-local) ----
    const float* al = attn + (size_t)bq * 96 + head * 12;
    float lg[12];
    float mx = -1e30f;
    #pragma unroll
    for (int i = 0; i < 12; i++) { lg[i] = al[i]; mx = fmaxf(mx, lg[i]); }
    float ssum = 0.f;
    #pragma unroll
    for (int i = 0; i < 12; i++) { lg[i] = __expf(lg[i] - mx); ssum += lg[i]; }
    const float inv = 1.f / ssum;

    const float rx = ref[(size_t)bq * 2 + 0];
    const float ry = ref[(size_t)bq * 2 + 1];
    const float* ob = off + (size_t)bq * 192 + head * (LEVELS_ * POINTS_ * 2);

    float acc = 0.f;

    #pragma unroll
    for (int lvl = 0; lvl < LEVELS_; lvl++) {
        const int Hs    = (lvl == 0) ? 64 : (lvl == 1) ? 32 : 16;
        const int Wsz   = Hs;
        const int start = (lvl == 0) ? 0 : (lvl == 1) ? 4096 : 5120;
        const float* vb = v + ((size_t)b * NV_ + start) * C_ + head * HD_ + lane;

        #pragma unroll
        for (int p = 0; p < POINTS_; p++) {
            const float ox = ob[(lvl * POINTS_ + p) * 2 + 0];
            const float oy = ob[(lvl * POINTS_ + p) * 2 + 1];
            const float lx = fminf(fmaxf(rx + ox, 0.f), 1.f);
            const float ly = fminf(fmaxf(ry + oy, 0.f), 1.f);
            const float x = lx * (float)Wsz - 0.5f;
            const float y = ly * (float)Hs - 0.5f;
            const float x0f = floorf(x);
            const float y0f = floorf(y);
            const float wx1 = x - x0f;
            const float wy1 = y - y0f;
            const int x0 = (int)x0f;
            const int y0 = (int)y0f;
            const float aw = lg[lvl * POINTS_ + p] * inv;

            float pv = 0.f;
            #pragma unroll
            for (int dy = 0; dy < 2; dy++) {
                #pragma unroll
                for (int dx = 0; dx < 2; dx++) {
                    const int ix = x0 + dx;
                    const int iy = y0 + dy;
                    const float w = (dx ? wx1 : 1.f - wx1) * (dy ? wy1 : 1.f - wy1);
                    const bool valid = (ix >= 0) & (ix < Wsz) & (iy >= 0) & (iy < Hs);
                    const int cx = min(max(ix, 0), Wsz - 1);
                    const int cy = min(max(iy, 0), Hs - 1);
                    const int idx = cy * Wsz + cx;
                    const float g = vb[(size_t)idx * C_];
                    pv += valid ? (w * g) : 0.f;
                }
            }
            acc = fmaf(aw, pv, acc);
        }
    }

    out[(size_t)bq * C_ + head * HD_ + lane] = acc;
}

// ---------------- launch ----------------
extern "C" void kernel_launch(void* const* d_in, const int* in_sizes, int n_in,
                              void* d_out, int out_size)
{
    const float* query = (const float*)d_in[0];   // (B,NQ,C)
    const float* refp  = (const float*)d_in[1];   // (B,NQ,2)
    const float* value = (const float*)d_in[2];   // (B,NV,C)
    const float* Wv    = (const float*)d_in[3];   // (C,C)
    const float* bv    = (const float*)d_in[4];   // (C)
    const float* Woff  = (const float*)d_in[5];   // (192,C)
    const float* boff  = (const float*)d_in[6];   // (192)
    const float* Wa    = (const float*)d_in[7];   // (96,C)
    const float* ba    = (const float*)d_in[8];   // (96)
    const float* Wo    = (const float*)d_in[9];   // (C,C)
    const float* bo    = (const float*)d_in[10];  // (C)
    float* out = (float*)d_out;

    float *p_v, *p_off, *p_attn, *p_tmp;
    cudaGetSymbolAddress((void**)&p_v,    g_v);
    cudaGetSymbolAddress((void**)&p_off,  g_off);
    cudaGetSymbolAddress((void**)&p_attn, g_attn);
    cudaGetSymbolAddress((void**)&p_tmp,  g_tmp);

    constexpr int BM = 64, BN = 64, BK = 16, TM = 4, TN = 4;
    const dim3 blk(256);
    const int grid_m = (M_ROWS + BM - 1) / BM;   // 168

    // 1) v = value @ Wv^T + bv   (M=10752, N=256)
    {
        dim3 grid((C_ + BN - 1) / BN, grid_m);
        gemm_bias_tn<BM, BN, BK, TM, TN><<<grid, blk>>>(value, Wv, bv, p_v,
                                                        M_ROWS, C_, K_DIM);
    }
    // 2) off = query @ Woff^T + boff   (N=192)
    {
        dim3 grid((192 + BN - 1) / BN, grid_m);
        gemm_bias_tn<BM, BN, BK, TM, TN><<<grid, blk>>>(query, Woff, boff, p_off,
                                                        M_ROWS, 192, K_DIM);
    }
    // 3) attn logits = query @ Wa^T + ba   (N=96)
    {
        dim3 grid((96 + BN - 1) / BN, grid_m);
        gemm_bias_tn<BM, BN, BK, TM, TN><<<grid, blk>>>(query, Wa, ba, p_attn,
                                                        M_ROWS, 96, K_DIM);
    }
    // 4) sampling: one warp per (b, q, head)
    {
        const int total_warps = B_ * NQ_ * HEADS_;     // 86016
        const int threads = 256;
        const int warps_per_block = threads / 32;
        const int blocks = (total_warps + warps_per_block - 1) / warps_per_block;
        msda_sample_kernel<<<blocks, threads>>>(p_v, refp, p_off, p_attn, p_tmp);
    }
    // 5) out = tmp @ Wo^T + bo   (N=256)
    {
        dim3 grid((C_ + BN - 1) / BN, grid_m);
        gemm_bias_tn<BM, BN, BK, TM, TN><<<grid, blk>>>(p_tmp, Wo, bo, out,
                                                        M_ROWS, C_, K_DIM);
    }
}

// round 2
// speedup vs baseline: 2.1715x; 2.1715x over previous
#include <cuda_runtime.h>
#include <cuda_bf16.h>
#include <math.h>

// ---------------- problem constants ----------------
#define B_    2
#define NQ_   5376
#define NV_   5376
#define C_    256
#define HEADS_ 8
#define HD_   32
#define LEVELS_ 3
#define POINTS_ 4
#define K_DIM 256
#define M_ROWS (B_ * NQ_)   // 10752
#define NPT   (LEVELS_ * POINTS_)  // 12

// ---------------- scratch (no allocations allowed) ----------------
__device__ float g_v[(size_t)B_ * NV_ * C_];          // value @ Wv^T + bv
__device__ float g_off[(size_t)B_ * NQ_ * 192];       // query @ Woff^T + boff
__device__ float g_attn[(size_t)B_ * NQ_ * 96];       // query @ Wa^T + ba (pre-softmax)
__device__ float g_tmp[(size_t)B_ * NQ_ * C_];        // sampled output (b,q,h*hd)
__device__ int4   g_sidx[(size_t)B_ * NQ_ * HEADS_ * NPT]; // 4 corner base indices
__device__ float4 g_sw[(size_t)B_ * NQ_ * HEADS_ * NPT];   // 4 corner weights (aw folded in)

// ---------------- SGEMM: C = A(MxK) * W(NxK)^T + bias ----------------
// BM=128, BN=128, BK=16, 256 threads, 8x8 per-thread tile.
// Requires: M % BM == 0, K % BK == 0 (holds: M=10752, K=256). N guarded.
template<int BM, int BN, int BK, int TM, int TN>
__global__ __launch_bounds__(256, 2)
void sgemm_tn(const float* __restrict__ A,
              const float* __restrict__ W,
              const float* __restrict__ bias,
              float* __restrict__ C,
              int M, int N, int K)
{
    __shared__ float As[BK][BM];
    __shared__ float Ws[BK][BN];

    const int tid = threadIdx.x;
    const int tx = tid % (BN / TN);     // 0..15
    const int ty = tid / (BN / TN);     // 0..15
    const int bm = blockIdx.y * BM;
    const int bn = blockIdx.x * BN;

    // load mapping: 128 rows x 16 k = 512 float4; 256 threads -> 2 float4 each
    const int lrow = tid >> 2;          // 0..63
    const int lk4  = (tid & 3) * 4;     // 0,4,8,12

    float acc[TM][TN];
    #pragma unroll
    for (int i = 0; i < TM; i++)
        #pragma unroll
        for (int j = 0; j < TN; j++) acc[i][j] = 0.f;

    for (int k0 = 0; k0 < K; k0 += BK) {
        // ---- A tile (no guards: M % BM == 0) ----
        #pragma unroll
        for (int r = 0; r < 2; r++) {
            const int row = lrow + r * 64;
            const float4 v4 = *(const float4*)&A[(size_t)(bm + row) * K + k0 + lk4];
            As[lk4 + 0][row] = v4.x;
            As[lk4 + 1][row] = v4.y;
            As[lk4 + 2][row] = v4.z;
            As[lk4 + 3][row] = v4.w;
        }
        // ---- W tile (guard N) ----
        #pragma unroll
        for (int r = 0; r < 2; r++) {
            const int row = lrow + r * 64;
            float4 v4 = make_float4(0.f, 0.f, 0.f, 0.f);
            if (bn + row < N)
                v4 = *(const float4*)&W[(size_t)(bn + row) * K + k0 + lk4];
            Ws[lk4 + 0][row] = v4.x;
            Ws[lk4 + 1][row] = v4.y;
            Ws[lk4 + 2][row] = v4.z;
            Ws[lk4 + 3][row] = v4.w;
        }
        __syncthreads();

        #pragma unroll
        for (int kk = 0; kk < BK; kk++) {
            float a_frag[TM], w_frag[TN];
            #pragma unroll
            for (int i = 0; i < TM; i += 4)
                *(float4*)&a_frag[i] = *(const float4*)&As[kk][ty * TM + i];
            #pragma unroll
            for (int j = 0; j < TN; j += 4)
                *(float4*)&w_frag[j] = *(const float4*)&Ws[kk][tx * TN + j];
            #pragma unroll
            for (int i = 0; i < TM; i++)
                #pragma unroll
                for (int j = 0; j < TN; j++)
                    acc[i][j] = fmaf(a_frag[i], w_frag[j], acc[i][j]);
        }
        __syncthreads();
    }

    #pragma unroll
    for (int i = 0; i < TM; i++) {
        const int gm = bm + ty * TM + i;
        #pragma unroll
        for (int j = 0; j < TN; j++) {
            const int gn = bn + tx * TN + j;
            if (gn < N)
                C[(size_t)gm * N + gn] = acc[i][j] + bias[gn];
        }
    }
}

// ---------------- prep: one thread per (b*q, head) ----------------
// softmax over 12 logits, bilinear setup; writes per-point int4 corner base
// indices (full element offsets into v, minus the lane/channel) and float4
// corner weights with the attention weight folded in (0 if invalid corner).
__global__ void msda_prep_kernel(const float* __restrict__ ref,
                                 const float* __restrict__ off,
                                 const float* __restrict__ attn,
                                 int4* __restrict__ sidx,
                                 float4* __restrict__ sw)
{
    const int t = blockIdx.x * blockDim.x + threadIdx.x;
    const int total = B_ * NQ_ * HEADS_;
    if (t >= total) return;

    const int head = t % HEADS_;
    const int bq   = t / HEADS_;
    const int b    = bq / NQ_;

    // softmax over this head's 12 logits
    const float* al = attn + (size_t)bq * 96 + head * NPT;
    float lg[NPT];
    float mx = -1e30f;
    #pragma unroll
    for (int i = 0; i < NPT; i++) { lg[i] = al[i]; mx = fmaxf(mx, lg[i]); }
    float ssum = 0.f;
    #pragma unroll
    for (int i = 0; i < NPT; i++) { lg[i] = __expf(lg[i] - mx); ssum += lg[i]; }
    const float inv = 1.f / ssum;

    const float rx = ref[(size_t)bq * 2 + 0];
    const float ry = ref[(size_t)bq * 2 + 1];
    const float* ob = off + (size_t)bq * 192 + head * (NPT * 2);

    const size_t obase = (size_t)t * NPT;

    #pragma unroll
    for (int lvl = 0; lvl < LEVELS_; lvl++) {
        const int Hs    = (lvl == 0) ? 64 : (lvl == 1) ? 32 : 16;
        const int Wsz   = Hs;
        const int start = (lvl == 0) ? 0 : (lvl == 1) ? 4096 : 5120;
        const int vbase = ((b * NV_) + start) * C_ + head * HD_;

        #pragma unroll
        for (int p = 0; p < POINTS_; p++) {
            const int pp = lvl * POINTS_ + p;
            const float ox = ob[pp * 2 + 0];
            const float oy = ob[pp * 2 + 1];
            const float lx = fminf(fmaxf(rx + ox, 0.f), 1.f);
            const float ly = fminf(fmaxf(ry + oy, 0.f), 1.f);
            const float x = lx * (float)Wsz - 0.5f;
            const float y = ly * (float)Hs - 0.5f;
            const float x0f = floorf(x);
            const float y0f = floorf(y);
            const float wx1 = x - x0f;
            const float wy1 = y - y0f;
            const int x0 = (int)x0f;
            const int y0 = (int)y0f;
            const float aw = lg[pp] * inv;

            int   ci[4];
            float cw[4];
            #pragma unroll
            for (int dy = 0; dy < 2; dy++) {
                #pragma unroll
                for (int dx = 0; dx < 2; dx++) {
                    const int ix = x0 + dx;
                    const int iy = y0 + dy;
                    const float w = (dx ? wx1 : 1.f - wx1) * (dy ? wy1 : 1.f - wy1);
                    const bool valid = (ix >= 0) & (ix < Wsz) & (iy >= 0) & (iy < Hs);
                    const int cx = min(max(ix, 0), Wsz - 1);
                    const int cy = min(max(iy, 0), Hs - 1);
                    ci[dy * 2 + dx] = vbase + (cy * Wsz + cx) * C_;
                    cw[dy * 2 + dx] = valid ? (w * aw) : 0.f;
                }
            }
            sidx[obase + pp] = make_int4(ci[0], ci[1], ci[2], ci[3]);
            sw[obase + pp]   = make_float4(cw[0], cw[1], cw[2], cw[3]);
        }
    }
}

// ---------------- gather: one warp per (b*q, head), lane = channel ----------------
__global__ void msda_gather_kernel(const float* __restrict__ v,
                                   const int4* __restrict__ sidx,
                                   const float4* __restrict__ sw,
                                   float* __restrict__ out)
{
    const int warp = (blockIdx.x * blockDim.x + threadIdx.x) >> 5;
    const int lane = threadIdx.x & 31;
    const int total = B_ * NQ_ * HEADS_;
    if (warp >= total) return;

    const int head = warp % HEADS_;
    const int bq   = warp / HEADS_;
    const size_t base = (size_t)warp * NPT;

    float acc = 0.f;
    #pragma unroll
    for (int p = 0; p < NPT; p++) {
        const int4   i4 = sidx[base + p];
        const float4 w4 = sw[base + p];
        acc = fmaf(w4.x, __ldg(v + i4.x + lane), acc);
        acc = fmaf(w4.y, __ldg(v + i4.y + lane), acc);
        acc = fmaf(w4.z, __ldg(v + i4.z + lane), acc);
        acc = fmaf(w4.w, __ldg(v + i4.w + lane), acc);
    }

    out[(size_t)bq * C_ + head * HD_ + lane] = acc;
}

// ---------------- launch ----------------
extern "C" void kernel_launch(void* const* d_in, const int* in_sizes, int n_in,
                              void* d_out, int out_size)
{
    const float* query = (const float*)d_in[0];   // (B,NQ,C)
    const float* refp  = (const float*)d_in[1];   // (B,NQ,2)
    const float* value = (const float*)d_in[2];   // (B,NV,C)
    const float* Wv    = (const float*)d_in[3];   // (C,C)
    const float* bv    = (const float*)d_in[4];   // (C)
    const float* Woff  = (const float*)d_in[5];   // (192,C)
    const float* boff  = (const float*)d_in[6];   // (192)
    const float* Wa    = (const float*)d_in[7];   // (96,C)
    const float* ba    = (const float*)d_in[8];   // (96)
    const float* Wo    = (const float*)d_in[9];   // (C,C)
    const float* bo    = (const float*)d_in[10];  // (C)
    float* out = (float*)d_out;

    float *p_v, *p_off, *p_attn, *p_tmp;
    int4 *p_sidx; float4 *p_sw;
    cudaGetSymbolAddress((void**)&p_v,    g_v);
    cudaGetSymbolAddress((void**)&p_off,  g_off);
    cudaGetSymbolAddress((void**)&p_attn, g_attn);
    cudaGetSymbolAddress((void**)&p_tmp,  g_tmp);
    cudaGetSymbolAddress((void**)&p_sidx, g_sidx);
    cudaGetSymbolAddress((void**)&p_sw,   g_sw);

    constexpr int BM = 128, BN = 128, BK = 16, TM = 8, TN = 8;
    const dim3 blk(256);
    const int grid_m = M_ROWS / BM;   // 84

    // 1) v = value @ Wv^T + bv   (N=256)
    {
        dim3 grid((C_ + BN - 1) / BN, grid_m);
        sgemm_tn<BM, BN, BK, TM, TN><<<grid, blk>>>(value, Wv, bv, p_v,
                                                    M_ROWS, C_, K_DIM);
    }
    // 2) off = query @ Woff^T + boff   (N=192)
    {
        dim3 grid((192 + BN - 1) / BN, grid_m);
        sgemm_tn<BM, BN, BK, TM, TN><<<grid, blk>>>(query, Woff, boff, p_off,
                                                    M_ROWS, 192, K_DIM);
    }
    // 3) attn logits = query @ Wa^T + ba   (N=96)
    {
        dim3 grid((96 + BN - 1) / BN, grid_m);
        sgemm_tn<BM, BN, BK, TM, TN><<<grid, blk>>>(query, Wa, ba, p_attn,
                                                    M_ROWS, 96, K_DIM);
    }
    // 4) prep: softmax + bilinear setup, one thread per (b,q,head)
    {
        const int total = B_ * NQ_ * HEADS_;   // 86016
        msda_prep_kernel<<<(total + 255) / 256, 256>>>(refp, p_off, p_attn,
                                                       p_sidx, p_sw);
    }
    // 5) gather: one warp per (b,q,head)
    {
        const int total_warps = B_ * NQ_ * HEADS_;
        const int blocks = (total_warps * 32 + 255) / 256;
        msda_gather_kernel<<<blocks, 256>>>(p_v, p_sidx, p_sw, p_tmp);
    }
    // 6) out = tmp @ Wo^T + bo   (N=256)
    {
        dim3 grid((C_ + BN - 1) / BN, grid_m);
        sgemm_tn<BM, BN, BK, TM, TN><<<grid, blk>>>(p_tmp, Wo, bo, out,
                                                    M_ROWS, C_, K_DIM);
    }
}

// round 5
// speedup vs baseline: 4.6049x; 2.1205x over previous
#include <cuda_runtime.h>
#include <cuda_bf16.h>
#include <stdint.h>
#include <math.h>

// ---------------- problem constants ----------------
#define B_    2
#define NQ_   5376
#define NV_   5376
#define C_    256
#define HEADS_ 8
#define HD_   32
#define NPT   12
#define KD    256
#define MR    10752       // B*NQ

// ---------------- scratch ----------------
__device__ float g_v[(size_t)MR * C_];
__device__ float g_off[(size_t)MR * 192];
__device__ float g_attn[(size_t)MR * 96];
__device__ float g_tmp[(size_t)MR * C_];

// ---------------- helpers ----------------
__device__ __forceinline__ uint32_t smem_u32(const void* p) {
    uint32_t a;
    asm("{ .reg .u64 t; cvta.to.shared.u64 t, %1; cvt.u32.u64 %0, t; }" : "=r"(a) : "l"(p));
    return a;
}

// pack two floats to bf16x2 (lo = x, hi = y), round-to-nearest
__device__ __forceinline__ uint32_t pack_bf2(float x, float y) {
    uint32_t r;
    asm("cvt.rn.bf16x2.f32 %0, %1, %2;" : "=r"(r) : "f"(y), "f"(x));
    return r;
}

#define LDM4(r, addr) \
    asm volatile("ldmatrix.sync.aligned.m8n8.x4.shared.b16 {%0,%1,%2,%3}, [%4];" \
        : "=r"((r)[0]), "=r"((r)[1]), "=r"((r)[2]), "=r"((r)[3]) : "r"(addr))

#define MMA_BF16(d, a, b0, b1) \
    asm volatile("mma.sync.aligned.m16n8k16.row.col.f32.bf16.bf16.f32 " \
        "{%0,%1,%2,%3}, {%4,%5,%6,%7}, {%8,%9}, {%0,%1,%2,%3};" \
        : "+f"((d)[0]), "+f"((d)[1]), "+f"((d)[2]), "+f"((d)[3]) \
        : "r"((a)[0]), "r"((a)[1]), "r"((a)[2]), "r"((a)[3]), "r"(b0), "r"(b1))

// ---------------- split-bf16 mma.sync GEMM ----------------
// C[M, Ntrue] = A[M, 256] @ W[Ntrue, 256]^T + bias (fp32 in/out)
// BM=128, BN=128, BK=32, 256 threads (8 warps, 4x2 warp grid, 32x64 warp tile)
// smem row stride S=40 bf16 (80B) -> conflict-free ldmatrix
#define S_ 40

__global__ __launch_bounds__(256)
void gemm_mma(const float* __restrict__ A, const float* __restrict__ W,
              const float* __restrict__ bias, float* __restrict__ Cc, int Ntrue)
{
    __shared__ __align__(16) __nv_bfloat16 sAhi[128 * S_];
    __shared__ __align__(16) __nv_bfloat16 sAlo[128 * S_];
    __shared__ __align__(16) __nv_bfloat16 sWhi[128 * S_];
    __shared__ __align__(16) __nv_bfloat16 sWlo[128 * S_];

    const int tid  = threadIdx.x;
    const int wid  = tid >> 5;
    const int lane = tid & 31;
    const int wm   = wid >> 1;          // 0..3 : 32-row strip
    const int wn   = wid & 1;           // 0..1 : 64-col strip
    const int bm   = blockIdx.y * 128;
    const int bn   = blockIdx.x * 128;
    const int wrows = Ntrue - bn;       // valid W rows in this tile

    const uint32_t uAhi = smem_u32(sAhi);
    const uint32_t uAlo = smem_u32(sAlo);
    const uint32_t uWhi = smem_u32(sWhi);
    const uint32_t uWlo = smem_u32(sWlo);

    float acc[2][8][4];
    #pragma unroll
    for (int i = 0; i < 2; i++)
        #pragma unroll
        for (int j = 0; j < 8; j++)
            #pragma unroll
            for (int k = 0; k < 4; k++) acc[i][j][k] = 0.f;

    // ldmatrix lane addressing (element offsets within tile)
    const int a_row = lane & 15;
    const int a_kc  = (lane & 16) ? 8 : 0;
    const int b_row = (lane & 7) + ((lane & 16) ? 8 : 0);
    const int b_kc  = (lane & 8) ? 8 : 0;

    for (int k0 = 0; k0 < KD; k0 += 32) {
        __syncthreads();
        // ---- stage A (M % 128 == 0, no row guard) ----
        #pragma unroll
        for (int i = 0; i < 4; i++) {
            const int f4  = tid + i * 256;       // 0..1023
            const int row = f4 >> 3;             // 0..127
            const int col = (f4 & 7) << 2;       // 0..28
            const float4 v = *(const float4*)&A[(size_t)(bm + row) * KD + k0 + col];
            const uint32_t h01 = pack_bf2(v.x, v.y);
            const uint32_t h23 = pack_bf2(v.z, v.w);
            const float hx = __uint_as_float(h01 << 16);
            const float hy = __uint_as_float(h01 & 0xFFFF0000u);
            const float hz = __uint_as_float(h23 << 16);
            const float hw = __uint_as_float(h23 & 0xFFFF0000u);
            const uint32_t l01 = pack_bf2(v.x - hx, v.y - hy);
            const uint32_t l23 = pack_bf2(v.z - hz, v.w - hw);
            const int e = row * S_ + col;
            *(uint2*)(sAhi + e) = make_uint2(h01, h23);
            *(uint2*)(sAlo + e) = make_uint2(l01, l23);
        }
        // ---- stage W (guard rows >= wrows: zeros) ----
        #pragma unroll
        for (int i = 0; i < 4; i++) {
            const int f4  = tid + i * 256;
            const int row = f4 >> 3;
            const int col = (f4 & 7) << 2;
            float4 v = make_float4(0.f, 0.f, 0.f, 0.f);
            if (row < wrows)
                v = *(const float4*)&W[(size_t)(bn + row) * KD + k0 + col];
            const uint32_t h01 = pack_bf2(v.x, v.y);
            const uint32_t h23 = pack_bf2(v.z, v.w);
            const float hx = __uint_as_float(h01 << 16);
            const float hy = __uint_as_float(h01 & 0xFFFF0000u);
            const float hz = __uint_as_float(h23 << 16);
            const float hw = __uint_as_float(h23 & 0xFFFF0000u);
            const uint32_t l01 = pack_bf2(v.x - hx, v.y - hy);
            const uint32_t l23 = pack_bf2(v.z - hz, v.w - hw);
            const int e = row * S_ + col;
            *(uint2*)(sWhi + e) = make_uint2(h01, h23);
            *(uint2*)(sWlo + e) = make_uint2(l01, l23);
        }
        __syncthreads();

        // ---- compute: 2 k-steps of 16 ----
        #pragma unroll
        for (int ks = 0; ks < 2; ks++) {
            const int kb = ks * 16;
            uint32_t ah[2][4], al[2][4];
            #pragma unroll
            for (int mf = 0; mf < 2; mf++) {
                const int e = (wm * 32 + mf * 16 + a_row) * S_ + kb + a_kc;
                LDM4(ah[mf], uAhi + e * 2);
                LDM4(al[mf], uAlo + e * 2);
            }
            #pragma unroll
            for (int nf = 0; nf < 4; nf++) {
                uint32_t bh[4], bl[4];
                const int e = (wn * 64 + nf * 16 + b_row) * S_ + kb + b_kc;
                LDM4(bh, uWhi + e * 2);
                LDM4(bl, uWlo + e * 2);
                #pragma unroll
                for (int mf = 0; mf < 2; mf++) {
                    MMA_BF16(acc[mf][nf * 2 + 0], ah[mf], bh[0], bh[1]);
                    MMA_BF16(acc[mf][nf * 2 + 1], ah[mf], bh[2], bh[3]);
                    MMA_BF16(acc[mf][nf * 2 + 0], ah[mf], bl[0], bl[1]);
                    MMA_BF16(acc[mf][nf * 2 + 1], ah[mf], bl[2], bl[3]);
                    MMA_BF16(acc[mf][nf * 2 + 0], al[mf], bh[0], bh[1]);
                    MMA_BF16(acc[mf][nf * 2 + 1], al[mf], bh[2], bh[3]);
                }
            }
        }
    }

    // ---- epilogue: direct stores with bias ----
    const int grp  = lane >> 2;
    const int tid4 = lane & 3;
    #pragma unroll
    for (int mf = 0; mf < 2; mf++) {
        const int row0 = bm + wm * 32 + mf * 16 + grp;
        #pragma unroll
        for (int nf = 0; nf < 8; nf++) {
            const int gn = bn + wn * 64 + nf * 8 + tid4 * 2;
            if (gn < Ntrue) {
                const float bb0 = bias[gn];
                const float bb1 = bias[gn + 1];
                *(float2*)&Cc[(size_t)row0 * Ntrue + gn] =
                    make_float2(acc[mf][nf][0] + bb0, acc[mf][nf][1] + bb1);
                *(float2*)&Cc[(size_t)(row0 + 8) * Ntrue + gn] =
                    make_float2(acc[mf][nf][2] + bb0, acc[mf][nf][3] + bb1);
            }
        }
    }
}

// ---------------- fused sampling: one warp per (b*q, head) ----------------
__global__ __launch_bounds__(256)
void msda_sample(const float* __restrict__ v, const float* __restrict__ ref,
                 const float* __restrict__ offp, const float* __restrict__ attn,
                 float* __restrict__ out)
{
    __shared__ int4   si[8][NPT];
    __shared__ float4 sw4[8][NPT];
    const int wslot = threadIdx.x >> 5;
    const int lane  = threadIdx.x & 31;
    const int warp  = blockIdx.x * 8 + wslot;
    const int head  = warp & 7;
    const int bq    = warp >> 3;
    const int b     = bq / NQ_;

    float lg = -1e30f;
    if (lane < NPT) lg = attn[(size_t)bq * 96 + head * NPT + lane];
    float mx = lg;
    #pragma unroll
    for (int o = 16; o; o >>= 1) mx = fmaxf(mx, __shfl_xor_sync(0xFFFFFFFFu, mx, o));
    float e = (lane < NPT) ? __expf(lg - mx) : 0.f;
    float s = e;
    #pragma unroll
    for (int o = 16; o; o >>= 1) s += __shfl_xor_sync(0xFFFFFFFFu, s, o);

    if (lane < NPT) {
        const float aw  = e / s;
        const int lvl   = lane >> 2;
        const int Hs    = 64 >> lvl;
        const int Wsz   = Hs;
        const int start = (lvl == 0) ? 0 : (lvl == 1) ? 4096 : 5120;
        const float rx = ref[(size_t)bq * 2 + 0];
        const float ry = ref[(size_t)bq * 2 + 1];
        const float ox = offp[(size_t)bq * 192 + head * 24 + lane * 2 + 0];
        const float oy = offp[(size_t)bq * 192 + head * 24 + lane * 2 + 1];
        const float lx = fminf(fmaxf(rx + ox, 0.f), 1.f);
        const float ly = fminf(fmaxf(ry + oy, 0.f), 1.f);
        const float x = lx * (float)Wsz - 0.5f;
        const float y = ly * (float)Hs - 0.5f;
        const float x0f = floorf(x);
        const float y0f = floorf(y);
        const float wx1 = x - x0f;
        const float wy1 = y - y0f;
        const int x0 = (int)x0f;
        const int y0 = (int)y0f;
        const int vb = (b * NV_ + start) * C_ + head * HD_;
        int ci[4]; float cw[4];
        #pragma unroll
        for (int dy = 0; dy < 2; dy++) {
            #pragma unroll
            for (int dx = 0; dx < 2; dx++) {
                const int ix = x0 + dx;
                const int iy = y0 + dy;
                const float w = (dx ? wx1 : 1.f - wx1) * (dy ? wy1 : 1.f - wy1);
                const bool valid = (ix >= 0) & (ix < Wsz) & (iy >= 0) & (iy < Hs);
                const int cx = min(max(ix, 0), Wsz - 1);
                const int cy = min(max(iy, 0), Hs - 1);
                ci[dy * 2 + dx] = vb + (cy * Wsz + cx) * C_;
                cw[dy * 2 + dx] = valid ? (w * aw) : 0.f;
            }
        }
        si[wslot][lane]  = make_int4(ci[0], ci[1], ci[2], ci[3]);
        sw4[wslot][lane] = make_float4(cw[0], cw[1], cw[2], cw[3]);
    }
    __syncwarp();

    float acc = 0.f;
    #pragma unroll
    for (int p = 0; p < NPT; p++) {
        const int4   i4 = si[wslot][p];
        const float4 w4 = sw4[wslot][p];
        acc = fmaf(w4.x, __ldg(v + i4.x + lane), acc);
        acc = fmaf(w4.y, __ldg(v + i4.y + lane), acc);
        acc = fmaf(w4.z, __ldg(v + i4.z + lane), acc);
        acc = fmaf(w4.w, __ldg(v + i4.w + lane), acc);
    }
    out[(size_t)bq * C_ + head * HD_ + lane] = acc;
}

// ---------------- launch ----------------
extern "C" void kernel_launch(void* const* d_in, const int* in_sizes, int n_in,
                              void* d_out, int out_size)
{
    const float* query = (const float*)d_in[0];
    const float* refp  = (const float*)d_in[1];
    const float* value = (const float*)d_in[2];
    const float* Wv    = (const float*)d_in[3];
    const float* bv    = (const float*)d_in[4];
    const float* Woff  = (const float*)d_in[5];
    const float* boff  = (const float*)d_in[6];
    const float* Wa    = (const float*)d_in[7];
    const float* ba    = (const float*)d_in[8];
    const float* Wo    = (const float*)d_in[9];
    const float* bo    = (const float*)d_in[10];
    float* out = (float*)d_out;

    float *p_v, *p_off, *p_attn, *p_tmp;
    cudaGetSymbolAddress((void**)&p_v,    g_v);
    cudaGetSymbolAddress((void**)&p_off,  g_off);
    cudaGetSymbolAddress((void**)&p_attn, g_attn);
    cudaGetSymbolAddress((void**)&p_tmp,  g_tmp);

    const dim3 blk(256);
    // 1) v = value @ Wv^T + bv       (N=256)
    gemm_mma<<<dim3(2, 84), blk>>>(value, Wv, bv, p_v, 256);
    // 2) off = query @ Woff^T + boff (N=192)
    gemm_mma<<<dim3(2, 84), blk>>>(query, Woff, boff, p_off, 192);
    // 3) attn = query @ Wa^T + ba    (N=96)
    gemm_mma<<<dim3(1, 84), blk>>>(query, Wa, ba, p_attn, 96);
    // 4) fused softmax + bilinear + gather
    msda_sample<<<(MR * HEADS_) / 8, 256>>>(p_v, refp, p_off, p_attn, p_tmp);
    // 5) out = tmp @ Wo^T + bo       (N=256)
    gemm_mma<<<dim3(2, 84), blk>>>(p_tmp, Wo, bo, out, 256);
}